// round 1
// baseline (speedup 1.0000x reference)
#include <cuda_runtime.h>
#include <cstdint>

// Sparsemax along last dim (d = 1024), one warp per row.
// Exact threshold via Michelot's algorithm warm-started at tau0 = max(z) - 1
// (valid since tau* >= max(z) - 1), converging in a handful of iterations.

constexpr int D   = 1024;   // last-dim size
constexpr int VPT = 32;     // values per lane (D / 32 lanes)

__global__ void __launch_bounds__(256)
sparsemax_kernel(const float* __restrict__ z, float* __restrict__ p, int rows) {
    const int warp_global = (blockIdx.x * blockDim.x + threadIdx.x) >> 5;
    const int lane = threadIdx.x & 31;
    if (warp_global >= rows) return;

    const float* zr = z + (size_t)warp_global * D;
    float*       pr = p + (size_t)warp_global * D;

    // ---- load row: 8 x float4 per lane, coalesced (lane*16B within 512B chunk) ----
    float v[VPT];
#pragma unroll
    for (int j = 0; j < 8; j++) {
        float4 t = *reinterpret_cast<const float4*>(zr + j * 128 + lane * 4);
        v[j * 4 + 0] = t.x;
        v[j * 4 + 1] = t.y;
        v[j * 4 + 2] = t.z;
        v[j * 4 + 3] = t.w;
    }

    // ---- row max (tree in regs + warp shuffle) ----
    float m = v[0];
#pragma unroll
    for (int i = 1; i < VPT; i++) m = fmaxf(m, v[i]);
#pragma unroll
    for (int o = 16; o > 0; o >>= 1)
        m = fmaxf(m, __shfl_xor_sync(0xffffffffu, m, o));

    // ---- Michelot fixed-point iteration, warm start tau0 = max - 1 ----
    // Invariant: tau <= tau*, active set {z > tau} shrinks monotonically.
    // Fixed point (tau_new == tau) is the exact sparsemax threshold.
    float tau = m - 1.0f;
#pragma unroll 1
    for (int iter = 0; iter < 64; iter++) {
        float s = 0.0f;
        float k = 0.0f;
#pragma unroll
        for (int i = 0; i < VPT; i++) {
            bool a = v[i] > tau;
            s += a ? v[i] : 0.0f;
            k += a ? 1.0f : 0.0f;
        }
#pragma unroll
        for (int o = 16; o > 0; o >>= 1) {
            s += __shfl_xor_sync(0xffffffffu, s, o);
            k += __shfl_xor_sync(0xffffffffu, k, o);
        }
        float ntau = (s - 1.0f) / k;   // k >= 1 always (z_max > tau)
        if (ntau == tau) break;        // exact fixed point reached
        tau = ntau;
    }

    // ---- write p = relu(z - tau), coalesced float4 stores ----
#pragma unroll
    for (int j = 0; j < 8; j++) {
        float4 t;
        t.x = fmaxf(v[j * 4 + 0] - tau, 0.0f);
        t.y = fmaxf(v[j * 4 + 1] - tau, 0.0f);
        t.z = fmaxf(v[j * 4 + 2] - tau, 0.0f);
        t.w = fmaxf(v[j * 4 + 3] - tau, 0.0f);
        *reinterpret_cast<float4*>(pr + j * 128 + lane * 4) = t;
    }
}

extern "C" void kernel_launch(void* const* d_in, const int* in_sizes, int n_in,
                              void* d_out, int out_size) {
    const float* z = (const float*)d_in[0];
    float* p = (float*)d_out;
    const int rows = in_sizes[0] / D;          // 8 * 4096 = 32768
    const int warps_per_block = 256 / 32;      // 8 rows per block
    const int grid = (rows + warps_per_block - 1) / warps_per_block;
    sparsemax_kernel<<<grid, 256>>>(z, p, rows);
}